// round 14
// baseline (speedup 1.0000x reference)
#include <cuda_runtime.h>
#include <cuda_bf16.h>
#include <cstdint>

#define BATCH 8
#define NN    2048
#define DD    128
#define LRELU_ALPHA 0.2f
#define LOG2E 1.4426950408889634f

// ---------------- device scratch (no allocation allowed) ----------------
__device__ __nv_bfloat16 g_hT[BATCH * DD * NN];   // transposed h, bf16 (B operand)
__device__ float g_x[BATCH * NN * DD];            // residual ping-pong
__device__ float g_s1[BATCH * NN];                // pre-scaled by log2(e)
__device__ float g_s2[BATCH * NN];                // pre-scaled by log2(e)
__device__ uint32_t g_mask[(size_t)BATCH * NN * (NN / 32)];   // adj bitmask, 4 MB

// ---------------- helpers ----------------
__device__ __forceinline__ uint32_t smem_u32(const void* p) {
    uint32_t a;
    asm("{ .reg .u64 t; cvta.to.shared.u64 t, %1; cvt.u32.u64 %0, t; }"
        : "=r"(a) : "l"(p));
    return a;
}
__device__ __forceinline__ void cpasync16(uint32_t dst, const void* src) {
    asm volatile("cp.async.cg.shared.global [%0], [%1], 16;"
                 :: "r"(dst), "l"(src) : "memory");
}
__device__ __forceinline__ void cp_commit() {
    asm volatile("cp.async.commit_group;" ::: "memory");
}
__device__ __forceinline__ void ldm4(uint32_t* r, uint32_t addr) {
    asm volatile("ldmatrix.sync.aligned.m8n8.x4.shared.b16 {%0,%1,%2,%3}, [%4];"
                 : "=r"(r[0]), "=r"(r[1]), "=r"(r[2]), "=r"(r[3]) : "r"(addr));
}
__device__ __forceinline__ void mma_bf16(float* c, const uint32_t* a,
                                         uint32_t b0, uint32_t b1) {
    asm volatile(
        "mma.sync.aligned.m16n8k16.row.col.f32.bf16.bf16.f32 "
        "{%0,%1,%2,%3}, {%4,%5,%6,%7}, {%8,%9}, {%0,%1,%2,%3};"
        : "+f"(c[0]), "+f"(c[1]), "+f"(c[2]), "+f"(c[3])
        : "r"(a[0]), "r"(a[1]), "r"(a[2]), "r"(a[3]), "r"(b0), "r"(b1));
}
__device__ __forceinline__ void mma_tf32(float* c, const uint32_t* a,
                                         uint32_t b0, uint32_t b1) {
    asm volatile(
        "mma.sync.aligned.m16n8k8.row.col.f32.tf32.tf32.f32 "
        "{%0,%1,%2,%3}, {%4,%5,%6,%7}, {%8,%9}, {%0,%1,%2,%3};"
        : "+f"(c[0]), "+f"(c[1]), "+f"(c[2]), "+f"(c[3])
        : "r"(a[0]), "r"(a[1]), "r"(a[2]), "r"(a[3]), "r"(b0), "r"(b1));
}
__device__ __forceinline__ uint32_t f2tf32(float v) {
    uint32_t r;
    asm("cvt.rna.tf32.f32 %0, %1;" : "=r"(r) : "f"(v));
    return r;
}
__device__ __forceinline__ float ex2(float v) {
    float r;
    asm("ex2.approx.f32 %0, %1;" : "=f"(r) : "f"(v));
    return r;
}
// swizzled byte offset of 16B chunk c (0..3) of row r in a [rows][32 bf16] tile
__device__ __forceinline__ uint32_t swz(int r, int c) {
    return (uint32_t)(r * 64 + (((c) ^ ((r >> 1) & 3)) << 4));
}
// pack two floats to bf16x2 {lo, hi}
__device__ __forceinline__ uint32_t pack_bf16x2(float lo, float hi) {
    uint32_t r;
    asm("cvt.rn.bf16x2.f32 %0, %1, %2;" : "=r"(r) : "f"(hi), "f"(lo));
    return r;
}

// ---------------- Kernel H: h = relu(x@W+b) via tf32 mma; HT bf16 + s1/s2 -------
// grid (32, 8, z). z==1 blocks (layer 0 only) pack adj into the bitmask instead
// (overlaps the DRAM-bound pack with layer-0 compute, one launch).
// Compute path: stage X [64][132] + FULL W [128][132] tf32, one barrier, then 16
// uninterrupted k8 steps. dyn smem 101376 B (sHT [128][66] bf16 reuses sW).
__global__ __launch_bounds__(256) void k_h(
    const float* __restrict__ X, const float* __restrict__ W,
    const float* __restrict__ bias,
    const float* __restrict__ a1, const float* __restrict__ a2,
    __nv_bfloat16* __restrict__ HT,
    float* __restrict__ S1, float* __restrict__ S2,
    const int* __restrict__ ADJ, uint32_t* __restrict__ MASKOUT)
{
    extern __shared__ char sm[];
    const int b   = blockIdx.y;
    const int i0  = blockIdx.x * 64;
    const int tid = threadIdx.x;
    const int warp = tid >> 5;
    const int lane = tid & 31;

    // ---------- pack path (layer 0 extra z-slice) ----------
    if (blockIdx.z == 1) {
#pragma unroll 1
        for (int rr = 0; rr < 8; rr++) {
            const int row = i0 + warp * 8 + rr;
            const int* ar = ADJ + ((size_t)b * NN + row) * NN;
            uint32_t* mr  = MASKOUT + ((size_t)b * NN + row) * (NN / 32);
#pragma unroll 4
            for (int w = 0; w < 16; w++) {
                int v0 = __ldg(ar + w * 128 +  0 + lane);
                int v1 = __ldg(ar + w * 128 + 32 + lane);
                int v2 = __ldg(ar + w * 128 + 64 + lane);
                int v3 = __ldg(ar + w * 128 + 96 + lane);
                uint32_t b0 = __ballot_sync(0xffffffffu, v0 != 0);
                uint32_t b1 = __ballot_sync(0xffffffffu, v1 != 0);
                uint32_t b2 = __ballot_sync(0xffffffffu, v2 != 0);
                uint32_t b3 = __ballot_sync(0xffffffffu, v3 != 0);
                if (lane == 0) *(uint4*)(mr + w * 4) = make_uint4(b0, b1, b2, b3);
            }
        }
        return;
    }

    // ---------- compute path ----------
    uint32_t* sX = (uint32_t*)sm;                       // [64][132]
    uint32_t* sW = (uint32_t*)(sm + 33792);             // [128][132]
    __nv_bfloat16* sHT = (__nv_bfloat16*)(sm + 33792);  // [128][66] (reuse)
    __shared__ float sS1p[2][64], sS2p[2][64];

    const int wm = warp >> 1;       // 0..3: m group (16 rows)
    const int wn = warp & 1;        // 0..1: n half (64 cols)

    // stage X tile (tf32) — 2048 float4, 8 per thread
    const float* Xb = X + ((size_t)b * NN + i0) * DD;
#pragma unroll
    for (int p = 0; p < 8; p++) {
        int gidx = p * 256 + tid;
        int row  = gidx >> 5;
        int c4   = (gidx & 31) << 2;
        float4 v = *(const float4*)(Xb + (size_t)row * DD + c4);
        *(uint4*)&sX[row * 132 + c4] =
            make_uint4(f2tf32(v.x), f2tf32(v.y), f2tf32(v.z), f2tf32(v.w));
    }
    // stage FULL W (tf32) — 4096 float4, 16 per thread
#pragma unroll
    for (int p = 0; p < 16; p++) {
        int gidx = p * 256 + tid;
        int r    = gidx >> 5;
        int c4   = (gidx & 31) << 2;
        float4 v = *(const float4*)(W + (size_t)r * DD + c4);
        *(uint4*)&sW[r * 132 + c4] =
            make_uint4(f2tf32(v.x), f2tf32(v.y), f2tf32(v.z), f2tf32(v.w));
    }
    __syncthreads();

    float acc[8][4];
#pragma unroll
    for (int nt = 0; nt < 8; nt++)
#pragma unroll
        for (int q = 0; q < 4; q++) acc[nt][q] = 0.f;

    const int rq = lane >> 2;
    const int kq = lane & 3;
    const int r0 = wm * 16 + rq;

#pragma unroll
    for (int k8 = 0; k8 < 16; k8++) {
        const int kk = k8 * 8 + kq;
        uint32_t a[4];
        a[0] = sX[r0 * 132 + kk];
        a[1] = sX[(r0 + 8) * 132 + kk];
        a[2] = sX[r0 * 132 + kk + 4];
        a[3] = sX[(r0 + 8) * 132 + kk + 4];
#pragma unroll
        for (int nt = 0; nt < 8; nt++) {
            const int n0 = wn * 64 + nt * 8 + rq;
            uint32_t b0 = sW[kk * 132 + n0];
            uint32_t b1 = sW[(kk + 4) * 132 + n0];
            mma_tf32(acc[nt], a, b0, b1);
        }
    }
    __syncthreads();   // sW dead; sHT reuse begins

    // epilogue: bias+relu, partial s1/s2 dots (pre-scaled by log2e), stage h^T
    const int rsm_lo = wm * 16 + rq;
    const int rsm_hi = rsm_lo + 8;
    float sum1_lo = 0.f, sum1_hi = 0.f, sum2_lo = 0.f, sum2_hi = 0.f;
#pragma unroll
    for (int nt = 0; nt < 8; nt++) {
        const int c = wn * 64 + nt * 8 + kq * 2;
        float bi0 = __ldg(bias + c), bi1 = __ldg(bias + c + 1);
        float h00 = fmaxf(acc[nt][0] + bi0, 0.f);
        float h01 = fmaxf(acc[nt][1] + bi1, 0.f);
        float h10 = fmaxf(acc[nt][2] + bi0, 0.f);
        float h11 = fmaxf(acc[nt][3] + bi1, 0.f);
        float2 A1 = *(const float2*)(a1 + c);
        float2 A2 = *(const float2*)(a2 + c);
        sum1_lo += h00 * A1.x + h01 * A1.y;
        sum1_hi += h10 * A1.x + h11 * A1.y;
        sum2_lo += h00 * A2.x + h01 * A2.y;
        sum2_hi += h10 * A2.x + h11 * A2.y;
        sHT[c * 66 + rsm_lo]       = __float2bfloat16(h00);
        sHT[(c + 1) * 66 + rsm_lo] = __float2bfloat16(h01);
        sHT[c * 66 + rsm_hi]       = __float2bfloat16(h10);
        sHT[(c + 1) * 66 + rsm_hi] = __float2bfloat16(h11);
    }
#pragma unroll
    for (int o = 1; o <= 2; o <<= 1) {
        sum1_lo += __shfl_xor_sync(0xffffffffu, sum1_lo, o);
        sum1_hi += __shfl_xor_sync(0xffffffffu, sum1_hi, o);
        sum2_lo += __shfl_xor_sync(0xffffffffu, sum2_lo, o);
        sum2_hi += __shfl_xor_sync(0xffffffffu, sum2_hi, o);
    }
    if (kq == 0) {
        sS1p[wn][rsm_lo] = sum1_lo;
        sS1p[wn][rsm_hi] = sum1_hi;
        sS2p[wn][rsm_lo] = sum2_lo;
        sS2p[wn][rsm_hi] = sum2_hi;
    }
    __syncthreads();
    if (tid < 64) {
        S1[(size_t)b * NN + i0 + tid] = (sS1p[0][tid] + sS1p[1][tid]) * LOG2E;
        S2[(size_t)b * NN + i0 + tid] = (sS2p[0][tid] + sS2p[1][tid]) * LOG2E;
    }

    // coalesced transposed writeout: thread pair = one d row (64B halves)
    const int drow = tid >> 1;
    const int half = tid & 1;
    const uint32_t sbase = smem_u32(sHT) + (uint32_t)(drow * 132 + half * 64);
    __nv_bfloat16* gdst = HT + ((size_t)b * DD + drow) * NN + i0 + half * 32;
#pragma unroll
    for (int g = 0; g < 4; g++) {
        uint32_t o0, o1, o2, o3;
        asm("ld.shared.b32 %0, [%1];" : "=r"(o0) : "r"(sbase + g * 16 + 0));
        asm("ld.shared.b32 %0, [%1];" : "=r"(o1) : "r"(sbase + g * 16 + 4));
        asm("ld.shared.b32 %0, [%1];" : "=r"(o2) : "r"(sbase + g * 16 + 8));
        asm("ld.shared.b32 %0, [%1];" : "=r"(o3) : "r"(sbase + g * 16 + 12));
        *(uint4*)((char*)gdst + g * 16) = make_uint4(o0, o1, o2, o3);
    }
}

// ---------------- Kernel F: producer/consumer fused softmax+aggregation ---------
// 64-j super-chunks (32 barrier iters). Warps 0-3 producers (ex2/mask/pack + B
// cp.async 3-deep 16KB ring + row sums), warps 4-7 consumers (ldmatrix+HMMA,
// each owns 32 d-cols x 64 rows). s1/s2 pre-scaled by log2e -> ex2.approx.
// dyn smem: s2s 8192 | sL 256 | msk 16640 | pbuf 2x8192 | Bbuf 3x16384 = 90624 B.
__global__ __launch_bounds__(256, 2) void k_fused(
    const __nv_bfloat16* __restrict__ HT, const uint32_t* __restrict__ MASK,
    const float* __restrict__ S1, const float* __restrict__ S2,
    const float* __restrict__ Xin, float* __restrict__ Xout)
{
    extern __shared__ char sm[];
    float*    s2s = (float*)sm;                       // [2048]
    float*    sL  = (float*)(sm + 8192);              // [64]
    uint32_t* msk = (uint32_t*)(sm + 8448);           // [64*65]
    const uint32_t pb = smem_u32(sm + 25088);         // 2 x 8192
    const uint32_t bb = smem_u32(sm + 41472);         // 3 x 16384
    __shared__ float s_red[8];

    const int b    = blockIdx.y;
    const int i0   = blockIdx.x * 64;
    const int tid  = threadIdx.x;
    const int warp = tid >> 5;
    const int lane = tid & 31;

    // ---- cooperative: s2 -> smem + global max; mask rows -> smem
    const float* s2g = S2 + (size_t)b * NN;
    float mx;
    {
        float4 v0 = *(const float4*)(s2g + tid * 8);
        float4 v1 = *(const float4*)(s2g + tid * 8 + 4);
        *(float4*)(s2s + tid * 8)     = v0;
        *(float4*)(s2s + tid * 8 + 4) = v1;
        mx = fmaxf(fmaxf(fmaxf(v0.x, v0.y), fmaxf(v0.z, v0.w)),
                   fmaxf(fmaxf(v1.x, v1.y), fmaxf(v1.z, v1.w)));
#pragma unroll
        for (int o = 16; o > 0; o >>= 1)
            mx = fmaxf(mx, __shfl_xor_sync(0xffffffffu, mx, o));
        if (lane == 0) s_red[warp] = mx;
    }
    {
        const uint32_t* mg = MASK + ((size_t)b * NN + i0) * 64;
#pragma unroll
        for (int k = 0; k < 16; k++) {
            int idx = tid + k * 256;
            int r = idx >> 6, w = idx & 63;
            msk[r * 65 + w] = mg[idx];
        }
    }
    __syncthreads();
    mx = fmaxf(fmaxf(fmaxf(s_red[0], s_red[1]), fmaxf(s_red[2], s_red[3])),
               fmaxf(fmaxf(s_red[4], s_red[5]), fmaxf(s_red[6], s_red[7])));

    const char* Hb = (const char*)(HT + (size_t)b * DD * NN);

    // ================= PRODUCER state =================
    const int prow = warp * 16 + (lane >> 1);   // producers: warps 0-3
    const int jh   = lane & 1;                  // j half (16 j)
    float s1r = 0.f, m = 0.f, l0 = 0.f, l1 = 0.f;
    if (warp < 4) {
        s1r = S1[(size_t)b * NN + i0 + prow];
        float t = s1r + mx;
        m = fmaxf(t, LRELU_ALPHA * t);
    }
    const uint32_t po0 = swz(prow, jh * 2);
    const uint32_t po1 = swz(prow, jh * 2 + 1);

    // compute p for 32-j chunk (2*s + c) into pbuf[s&1] tile c
    auto produce = [&](int s, int c) {
        const int kc = 2 * s + c;
        const uint32_t w = msk[prow * 65 + kc] >> (jh * 16);
        const float* sp = s2s + kc * 32 + jh * 16;
        float4 va = *(const float4*)(sp);
        float4 vb = *(const float4*)(sp + 4);
        float4 vc = *(const float4*)(sp + 8);
        float4 vd = *(const float4*)(sp + 12);
        float p[16];
        float z;
#define PCALC(i, val) \
        z = s1r + (val); z = fmaxf(z, LRELU_ALPHA * z); \
        z = ex2(z - m); p[i] = (w & (1u << (i))) ? z : 0.f;
        PCALC(0, va.x)  PCALC(1, va.y)  PCALC(2, va.z)  PCALC(3, va.w)
        PCALC(4, vb.x)  PCALC(5, vb.y)  PCALC(6, vb.z)  PCALC(7, vb.w)
        PCALC(8, vc.x)  PCALC(9, vc.y)  PCALC(10, vc.z) PCALC(11, vc.w)
        PCALC(12, vd.x) PCALC(13, vd.y) PCALC(14, vd.z) PCALC(15, vd.w)
#undef PCALC
        l0 += ((p[0] + p[1]) + (p[2] + p[3])) + ((p[4] + p[5]) + (p[6] + p[7]));
        l1 += ((p[8] + p[9]) + (p[10] + p[11])) + ((p[12] + p[13]) + (p[14] + p[15]));
        uint32_t r0 = pack_bf16x2(p[0], p[1]),  r1 = pack_bf16x2(p[2], p[3]);
        uint32_t r2 = pack_bf16x2(p[4], p[5]),  r3 = pack_bf16x2(p[6], p[7]);
        uint32_t r4 = pack_bf16x2(p[8], p[9]),  r5 = pack_bf16x2(p[10], p[11]);
        uint32_t r6 = pack_bf16x2(p[12], p[13]), r7 = pack_bf16x2(p[14], p[15]);
        const uint32_t tb = pb + (uint32_t)((s & 1) * 2 + c) * 4096;
        asm volatile("st.shared.v4.b32 [%0], {%1,%2,%3,%4};"
                     :: "r"(tb + po0), "r"(r0), "r"(r1), "r"(r2), "r"(r3));
        asm volatile("st.shared.v4.b32 [%0], {%1,%2,%3,%4};"
                     :: "r"(tb + po1), "r"(r4), "r"(r5), "r"(r6), "r"(r7));
    };
    // issue cp.async for B super-chunk ch (64 j = two 8KB tiles); 8x16B per thread
    auto loadB = [&](int ch) {
        const uint32_t dst = bb + (uint32_t)(ch % 3) * 16384;
        const char* src = Hb + (size_t)ch * 128;
#pragma unroll
        for (int q = 0; q < 8; q++) {
            const int ct  = q >> 2;
            const int idx = tid + (q & 3) * 128;
            const int r = idx >> 2, cc = idx & 3;
            cpasync16(dst + ct * 8192 + swz(r, cc),
                      src + (size_t)r * (NN * 2) + ct * 64 + cc * 16);
        }
        cp_commit();
    };

    // ================= CONSUMER state =================
    const int cw = warp - 4;                    // consumers: warps 4-7, 32 d-cols
    const int lr = lane & 15;
    const int lc = lane >> 4;
    uint32_t offA[4][2], offB[2][2];
#pragma unroll
    for (int mt = 0; mt < 4; mt++)
#pragma unroll
        for (int ss = 0; ss < 2; ss++)
            offA[mt][ss] = swz(mt * 16 + lr, 2 * ss + lc);
#pragma unroll
    for (int dg = 0; dg < 2; dg++)
#pragma unroll
        for (int ss = 0; ss < 2; ss++)
            offB[dg][ss] = swz(cw * 32 + dg * 16 + lr, 2 * ss + lc);

    float acc[4][4][4];
#pragma unroll
    for (int mt = 0; mt < 4; mt++)
#pragma unroll
        for (int n = 0; n < 4; n++)
#pragma unroll
            for (int q = 0; q < 4; q++) acc[mt][n][q] = 0.f;

    // ---- prologue
    if (warp < 4) {
        loadB(0); loadB(1);
        produce(0, 0); produce(0, 1);
        asm volatile("cp.async.wait_group 1;" ::: "memory");
    }
    __syncthreads();

    // ---- main loop: 32 super-chunks of 64 j
    for (int s = 0; s < 32; s++) {
        if (warp < 4) {
            if (s < 30) loadB(s + 2);
            if (s < 31) { produce(s + 1, 0); produce(s + 1, 1); }
            if (s < 30)      { asm volatile("cp.async.wait_group 1;" ::: "memory"); }
            else if (s == 30){ asm volatile("cp.async.wait_group 0;" ::: "memory"); }
        } else {
#pragma unroll
            for (int c = 0; c < 2; c++) {
                const uint32_t pt = pb + (uint32_t)((s & 1) * 2 + c) * 4096;
                const uint32_t bt = bb + (uint32_t)(s % 3) * 16384 + (uint32_t)c * 8192;
#pragma unroll
                for (int ss = 0; ss < 2; ss++) {
                    uint32_t a0[4], a1[4], a2[4], a3[4];
                    ldm4(a0, pt + offA[0][ss]);
                    ldm4(a1, pt + offA[1][ss]);
                    ldm4(a2, pt + offA[2][ss]);
                    ldm4(a3, pt + offA[3][ss]);
#pragma unroll
                    for (int dg = 0; dg < 2; dg++) {
                        uint32_t q[4];
                        ldm4(q, bt + offB[dg][ss]);
                        mma_bf16(acc[0][dg * 2 + 0], a0, q[0], q[2]);
                        mma_bf16(acc[0][dg * 2 + 1], a0, q[1], q[3]);
                        mma_bf16(acc[1][dg * 2 + 0], a1, q[0], q[2]);
                        mma_bf16(acc[1][dg * 2 + 1], a1, q[1], q[3]);
                        mma_bf16(acc[2][dg * 2 + 0], a2, q[0], q[2]);
                        mma_bf16(acc[2][dg * 2 + 1], a2, q[1], q[3]);
                        mma_bf16(acc[3][dg * 2 + 0], a3, q[0], q[2]);
                        mma_bf16(acc[3][dg * 2 + 1], a3, q[1], q[3]);
                    }
                }
            }
        }
        __syncthreads();
    }

    // ---- epilogue: producers publish l; consumers normalize + residual
    if (warp < 4) {
        float lf = l0 + l1;
        lf += __shfl_xor_sync(0xffffffffu, lf, 1);
        if (jh == 0) sL[prow] = lf;
    }
    __syncthreads();
    if (warp >= 4) {
#pragma unroll
        for (int mt = 0; mt < 4; mt++) {
            const int rl = mt * 16 + (lane >> 2);
            const int rh = rl + 8;
            const float invl = 1.0f / sL[rl];
            const float invh = 1.0f / sL[rh];
            const size_t gl = ((size_t)b * NN + i0 + rl) * DD;
            const size_t gh = ((size_t)b * NN + i0 + rh) * DD;
#pragma unroll
            for (int n = 0; n < 4; n++) {
                const int col = cw * 32 + n * 8 + (lane & 3) * 2;
                float2 xa = *(const float2*)(Xin + gl + col);
                float2 xb = *(const float2*)(Xin + gh + col);
                float2 oa, ob;
                oa.x = xa.x + acc[mt][n][0] * invl;
                oa.y = xa.y + acc[mt][n][1] * invl;
                ob.x = xb.x + acc[mt][n][2] * invh;
                ob.y = xb.y + acc[mt][n][3] * invh;
                *(float2*)(Xout + gl + col) = oa;
                *(float2*)(Xout + gh + col) = ob;
            }
        }
    }
}

// ---------------- host launcher ----------------
extern "C" void kernel_launch(void* const* d_in, const int* in_sizes, int n_in,
                              void* d_out, int out_size)
{
    (void)in_sizes; (void)n_in; (void)out_size;
    const float* x   = (const float*)d_in[0];
    const int*   adj = (const int*)d_in[1];
    const float* Wg  = (const float*)d_in[2];
    const float* bg  = (const float*)d_in[3];
    const float* aa  = (const float*)d_in[4];
    float* out = (float*)d_out;

    float *xbuf, *s1, *s2;
    __nv_bfloat16 *hT;
    uint32_t *msk;
    cudaGetSymbolAddress((void**)&xbuf, g_x);
    cudaGetSymbolAddress((void**)&s1,   g_s1);
    cudaGetSymbolAddress((void**)&s2,   g_s2);
    cudaGetSymbolAddress((void**)&hT,   g_hT);
    cudaGetSymbolAddress((void**)&msk,  g_mask);

    const int smemH = 33792 + 67584;                      // 101376 B
    const int smemF = 8192 + 256 + 16640 + 16384 + 49152; // 90624 B
    cudaFuncSetAttribute(k_h,     cudaFuncAttributeMaxDynamicSharedMemorySize, smemH);
    cudaFuncSetAttribute(k_fused, cudaFuncAttributeMaxDynamicSharedMemorySize, smemF);

    for (int l = 0; l < 3; l++) {
        const float* xin  = (l == 0) ? x : xbuf;
        float*       xout = (l == 2) ? out : xbuf;
        // layer 0 carries the adj-packing blocks as a 2nd grid.z slice
        dim3 gridH(NN / 64, BATCH, (l == 0) ? 2 : 1);
        k_h<<<gridH, 256, smemH>>>(
            xin, Wg + (size_t)l * DD * DD, bg + (size_t)l * DD,
            aa + (size_t)l * 2 * DD, aa + (size_t)l * 2 * DD + DD,
            hT, s1, s2, adj, msk);
        k_fused<<<dim3(NN / 64, BATCH), 256, smemF>>>(hT, msk, s1, s2, xin, xout);
    }
}